// round 7
// baseline (speedup 1.0000x reference)
#include <cuda_runtime.h>
#include <cuda_bf16.h>
#include <float.h>
#include <math.h>

// ---------------- problem constants ----------------
#define BB   16
#define EE   400
#define RR   624
#define NN   1024          // E + R
#define HSZ  512
#define HEADS 4
#define DK   128
#define DFF  2048
#define PROP 2
#define RTOKS 40

// ---------------- scratch (device globals; no allocs allowed) ----------------
__device__ float g_x[(long)BB*NN*HSZ];
__device__ float g_q[(long)BB*NN*HSZ];
__device__ float g_k[(long)BB*NN*HSZ];
__device__ float g_v[(long)BB*NN*HSZ];
__device__ float g_o[(long)BB*NN*HSZ];
__device__ float g_t[(long)BB*NN*HSZ];
__device__ float g_h[(long)BB*NN*DFF];
__device__ unsigned g_mask[(long)BB*NN*(NN/32)];   // adj bitmask, 2MB

// ---------------- helpers ----------------
__device__ __forceinline__ unsigned f2tf32(float x) {
    unsigned r;
    asm("cvt.rna.tf32.f32 %0, %1;" : "=r"(r) : "f"(x));
    return r;
}

__device__ __forceinline__ void mma_tf32(float* c, const unsigned* a, unsigned b0, unsigned b1) {
    asm volatile(
        "mma.sync.aligned.m16n8k8.row.col.f32.tf32.tf32.f32 "
        "{%0,%1,%2,%3}, {%4,%5,%6,%7}, {%8,%9}, {%0,%1,%2,%3};\n"
        : "+f"(c[0]), "+f"(c[1]), "+f"(c[2]), "+f"(c[3])
        : "r"(a[0]), "r"(a[1]), "r"(a[2]), "r"(a[3]), "r"(b0), "r"(b1));
}

// ---------------- gather: x = concat(ents, renc[rels]) ----------------
__global__ void __launch_bounds__(256) gather_kernel(
    const float* __restrict__ ents, const int* __restrict__ rels,
    const float* __restrict__ renc)
{
    long i = (long)blockIdx.x * 256 + threadIdx.x;          // float4 index
    const long TOT = (long)BB * NN * (HSZ / 4);
    if (i >= TOT) return;
    int c  = (int)(i & (HSZ/4 - 1));                        // 0..127
    long bn = i >> 7;
    int n  = (int)(bn & (NN - 1));
    int b  = (int)(bn >> 10);
    float4 v;
    if (n < EE) {
        v = ((const float4*)ents)[((long)b*EE + n)*(HSZ/4) + c];
    } else {
        int r = rels[b*RR + (n - EE)];
        v = ((const float4*)renc)[(long)r*(HSZ/4) + c];
    }
    ((float4*)g_x)[i] = v;
}

// ---------------- adj -> bitmask (32 cols per word) ----------------
__global__ void __launch_bounds__(256) mask_kernel(const int* __restrict__ adj)
{
    long i = (long)blockIdx.x * 256 + threadIdx.x;          // word index
    const long TOT = (long)BB * NN * (NN / 32);
    if (i >= TOT) return;
    const int* p = adj + i * 32;
    unsigned m = 0;
    #pragma unroll
    for (int t = 0; t < 8; t++) {
        int4 a = ((const int4*)p)[t];
        m |= (a.x ? 1u : 0u) << (t*4 + 0);
        m |= (a.y ? 1u : 0u) << (t*4 + 1);
        m |= (a.z ? 1u : 0u) << (t*4 + 2);
        m |= (a.w ? 1u : 0u) << (t*4 + 3);
    }
    g_mask[i] = m;
}

// ---------------- fused flash attention (masked) + residual ----------------
// Per block: 128 Q rows for one (b,h). 8 warps, warp w owns rows [w*16, w*16+16).
// smem: sQ[128][136], sKV[128][136] (K then V per tile), sP[128][136].
#define FL_STRIDE 136
#define FL_WORDS  (128 * FL_STRIDE)
#define FL_BYTES  (3 * FL_WORDS * 4)

__global__ void __launch_bounds__(256) flash_kernel(
    const float* __restrict__ Q, const float* __restrict__ K,
    const float* __restrict__ V, const float* __restrict__ X,
    float* __restrict__ O)
{
    extern __shared__ unsigned sm[];
    unsigned* sQ  = sm;
    unsigned* sKV = sm + FL_WORDS;
    unsigned* sP  = sm + 2 * FL_WORDS;

    int qt = blockIdx.x, h = blockIdx.y, b = blockIdx.z;
    int tid = threadIdx.x, warp = tid >> 5, lane = tid & 31;
    int gid = lane >> 2, tig = lane & 3;

    const float scale = 0.04419417382415922f;  // 1/sqrt(512)
    const long baserow = (long)b * NN;
    const int  hc = h * DK;

    // ---- load Q tile (scaled + tf32) ----
    {
        const float* src = Q + (baserow + qt*128) * HSZ + hc;
        for (int i = tid; i < 128*32; i += 256) {
            int r = i >> 5, c4 = (i & 31) * 4;
            float4 v = *(const float4*)(src + (long)r * HSZ + c4);
            unsigned* d = &sQ[r * FL_STRIDE + c4];
            d[0] = f2tf32(v.x * scale); d[1] = f2tf32(v.y * scale);
            d[2] = f2tf32(v.z * scale); d[3] = f2tf32(v.w * scale);
        }
    }

    float acc_o[16][4];
    #pragma unroll
    for (int nt = 0; nt < 16; nt++)
        #pragma unroll
        for (int i = 0; i < 4; i++) acc_o[nt][i] = 0.f;

    float m0 = -INFINITY, m1 = -INFINITY, l0 = 0.f, l1 = 0.f;

    const unsigned* mrow0 = g_mask + ((long)b*NN + qt*128 + warp*16 + gid) * (NN/32);
    const unsigned* mrow1 = mrow0 + 8 * (NN/32);

    for (int j = 0; j < NN/128; j++) {
        __syncthreads();   // prev O-gemm done reading sKV / first iter: pairs with K-load sync
        // ---- load K_j tile ----
        {
            const float* src = K + (baserow + j*128) * HSZ + hc;
            for (int i = tid; i < 128*32; i += 256) {
                int r = i >> 5, c4 = (i & 31) * 4;
                float4 v = *(const float4*)(src + (long)r * HSZ + c4);
                unsigned* d = &sKV[r * FL_STRIDE + c4];
                d[0] = f2tf32(v.x); d[1] = f2tf32(v.y);
                d[2] = f2tf32(v.z); d[3] = f2tf32(v.w);
            }
        }
        __syncthreads();

        // ---- S = Qs @ K^T  (warp: 16 rows x 128 cols) ----
        float acc_s[16][4];
        #pragma unroll
        for (int nt = 0; nt < 16; nt++)
            #pragma unroll
            for (int i = 0; i < 4; i++) acc_s[nt][i] = 0.f;

        #pragma unroll
        for (int ks = 0; ks < 16; ks++) {
            int k0 = ks * 8;
            unsigned a[4];
            const unsigned* ap = &sQ[(warp*16 + gid) * FL_STRIDE + k0 + tig];
            a[0] = ap[0]; a[1] = ap[8*FL_STRIDE]; a[2] = ap[4]; a[3] = ap[8*FL_STRIDE + 4];
            #pragma unroll
            for (int nt = 0; nt < 16; nt++) {
                const unsigned* bp = &sKV[(nt*8 + gid) * FL_STRIDE + k0 + tig];
                mma_tf32(acc_s[nt], a, bp[0], bp[4]);
            }
        }

        // ---- mask + online softmax ----
        unsigned mw0[4], mw1[4];
        #pragma unroll
        for (int w = 0; w < 4; w++) { mw0[w] = mrow0[j*4 + w]; mw1[w] = mrow1[j*4 + w]; }

        float tm0 = -INFINITY, tm1 = -INFINITY;
        #pragma unroll
        for (int nt = 0; nt < 16; nt++) {
            int c0 = nt*8 + tig*2;
            unsigned w = nt >> 2;
            int bi = c0 & 31;
            acc_s[nt][0] = ((mw0[w] >> bi)     & 1) ? acc_s[nt][0] : -1e30f;
            acc_s[nt][1] = ((mw0[w] >> (bi+1)) & 1) ? acc_s[nt][1] : -1e30f;
            acc_s[nt][2] = ((mw1[w] >> bi)     & 1) ? acc_s[nt][2] : -1e30f;
            acc_s[nt][3] = ((mw1[w] >> (bi+1)) & 1) ? acc_s[nt][3] : -1e30f;
            tm0 = fmaxf(tm0, fmaxf(acc_s[nt][0], acc_s[nt][1]));
            tm1 = fmaxf(tm1, fmaxf(acc_s[nt][2], acc_s[nt][3]));
        }
        tm0 = fmaxf(tm0, __shfl_xor_sync(0xffffffffu, tm0, 1));
        tm0 = fmaxf(tm0, __shfl_xor_sync(0xffffffffu, tm0, 2));
        tm1 = fmaxf(tm1, __shfl_xor_sync(0xffffffffu, tm1, 1));
        tm1 = fmaxf(tm1, __shfl_xor_sync(0xffffffffu, tm1, 2));

        float nm0 = fmaxf(m0, tm0), nm1 = fmaxf(m1, tm1);
        float f0 = __expf(m0 - nm0), f1 = __expf(m1 - nm1);

        float sum0 = 0.f, sum1 = 0.f;
        unsigned* pp = &sP[(warp*16 + gid) * FL_STRIDE + tig*2];
        #pragma unroll
        for (int nt = 0; nt < 16; nt++) {
            float p0 = __expf(acc_s[nt][0] - nm0);
            float p1 = __expf(acc_s[nt][1] - nm0);
            float p2 = __expf(acc_s[nt][2] - nm1);
            float p3 = __expf(acc_s[nt][3] - nm1);
            sum0 += p0 + p1; sum1 += p2 + p3;
            uint2 u0 = make_uint2(f2tf32(p0), f2tf32(p1));
            uint2 u1 = make_uint2(f2tf32(p2), f2tf32(p3));
            *(uint2*)(pp + nt*8)                  = u0;
            *(uint2*)(pp + nt*8 + 8*FL_STRIDE)    = u1;
        }
        sum0 += __shfl_xor_sync(0xffffffffu, sum0, 1);
        sum0 += __shfl_xor_sync(0xffffffffu, sum0, 2);
        sum1 += __shfl_xor_sync(0xffffffffu, sum1, 1);
        sum1 += __shfl_xor_sync(0xffffffffu, sum1, 2);

        l0 = l0 * f0 + sum0;  l1 = l1 * f1 + sum1;
        m0 = nm0;  m1 = nm1;
        #pragma unroll
        for (int nt = 0; nt < 16; nt++) {
            acc_o[nt][0] *= f0; acc_o[nt][1] *= f0;
            acc_o[nt][2] *= f1; acc_o[nt][3] *= f1;
        }

        __syncthreads();   // sKV(K) reads finished by all warps; P visible after next sync
        // ---- load V_j tile into sKV ([kvrow][dk]) ----
        {
            const float* src = V + (baserow + j*128) * HSZ + hc;
            for (int i = tid; i < 128*32; i += 256) {
                int r = i >> 5, c4 = (i & 31) * 4;
                float4 v = *(const float4*)(src + (long)r * HSZ + c4);
                unsigned* d = &sKV[r * FL_STRIDE + c4];
                d[0] = f2tf32(v.x); d[1] = f2tf32(v.y);
                d[2] = f2tf32(v.z); d[3] = f2tf32(v.w);
            }
        }
        __syncthreads();

        // ---- O += P @ V ----
        #pragma unroll
        for (int ks = 0; ks < 16; ks++) {
            int k0 = ks * 8;
            unsigned a[4];
            const unsigned* ap = &sP[(warp*16 + gid) * FL_STRIDE + k0 + tig];
            a[0] = ap[0]; a[1] = ap[8*FL_STRIDE]; a[2] = ap[4]; a[3] = ap[8*FL_STRIDE + 4];
            #pragma unroll
            for (int nt = 0; nt < 16; nt++) {
                const unsigned* bp = &sKV[(k0 + tig) * FL_STRIDE + nt*8 + gid];
                mma_tf32(acc_o[nt], a, bp[0], bp[4*FL_STRIDE]);
            }
        }
    }

    // ---- epilogue: O/l + residual X ----
    float inv0 = 1.f / l0, inv1 = 1.f / l1;
    long rbase = (baserow + qt*128 + warp*16 + gid) * HSZ + hc;
    #pragma unroll
    for (int nt = 0; nt < 16; nt++) {
        int c0 = nt*8 + tig*2;
        float2 x0 = *(const float2*)(X + rbase + c0);
        float2 x1 = *(const float2*)(X + rbase + 8*HSZ + c0);
        float2 o0 = make_float2(acc_o[nt][0]*inv0 + x0.x, acc_o[nt][1]*inv0 + x0.y);
        float2 o1 = make_float2(acc_o[nt][2]*inv1 + x1.x, acc_o[nt][3]*inv1 + x1.y);
        *(float2*)(O + rbase + c0)           = o0;
        *(float2*)(O + rbase + 8*HSZ + c0)   = o1;
    }
}

// ---------------- tensor-core tf32 GEMM: 128x128 block tile, K-chunk 32 ----------------
template<bool TRB>
__global__ void __launch_bounds__(256, 2) gemm_mma(
    const float* __restrict__ A, const float* __restrict__ B, float* __restrict__ C,
    int M, int N, int K, int lda, int ldb, int ldc,
    long sAb, long sAh, long sBb, long sBh, long sCb, long sCh,
    int H, float alpha,
    const float* __restrict__ bias,
    const float* __restrict__ prelu,
    const float* __restrict__ res)
{
    constexpr int PA = 40;
    constexpr int PB = 136;

    __shared__ unsigned As[128 * PA];
    __shared__ unsigned Bs[TRB ? 128 * PA : 32 * PB];

    int zb = blockIdx.z / H;
    int zh = blockIdx.z - zb * H;
    const float* Ab = A + zb * sAb + zh * sAh;
    const float* Bb = B + zb * sBb + zh * sBh;
    float*       Cb = C + zb * sCb + zh * sCh;
    const float* Rb = res ? (res + zb * sCb + zh * sCh) : nullptr;

    int bm = blockIdx.y << 7;
    int bn = blockIdx.x << 7;

    int tid  = threadIdx.x;
    int warp = tid >> 5, lane = tid & 31;
    int wm = warp >> 1, wn = warp & 1;
    int gid = lane >> 2, tig = lane & 3;

    float acc[2][8][4];
    #pragma unroll
    for (int mt = 0; mt < 2; mt++)
        #pragma unroll
        for (int nt = 0; nt < 8; nt++)
            #pragma unroll
            for (int i = 0; i < 4; i++) acc[mt][nt][i] = 0.f;

    const int ar0 = tid >> 3;
    const int acg = tid & 7;

    float4 ra[4], rb[4];
    const int nch = K >> 5;

    {
        const float* pa = Ab + (long)(bm + ar0) * lda + acg * 4;
        #pragma unroll
        for (int l = 0; l < 4; l++) ra[l] = *(const float4*)(pa + (long)(32 * l) * lda);
        if (TRB) {
            const float* pb = Bb + (long)(bn + ar0) * ldb + acg * 4;
            #pragma unroll
            for (int l = 0; l < 4; l++) rb[l] = *(const float4*)(pb + (long)(32 * l) * ldb);
        } else {
            const float* pb = Bb + (long)warp * ldb + bn + lane * 4;
            #pragma unroll
            for (int l = 0; l < 4; l++) rb[l] = *(const float4*)(pb + (long)(8 * l) * ldb);
        }
    }

    for (int c = 0; c < nch; c++) {
        #pragma unroll
        for (int l = 0; l < 4; l++) {
            uint4 u;
            u.x = f2tf32(ra[l].x); u.y = f2tf32(ra[l].y);
            u.z = f2tf32(ra[l].z); u.w = f2tf32(ra[l].w);
            *(uint4*)&As[(ar0 + 32 * l) * PA + acg * 4] = u;
        }
        #pragma unroll
        for (int l = 0; l < 4; l++) {
            uint4 u;
            u.x = f2tf32(rb[l].x); u.y = f2tf32(rb[l].y);
            u.z = f2tf32(rb[l].z); u.w = f2tf32(rb[l].w);
            if (TRB) *(uint4*)&Bs[(ar0 + 32 * l) * PA + acg * 4] = u;
            else     *(uint4*)&Bs[(warp + 8 * l) * PB + lane * 4] = u;
        }
        __syncthreads();

        if (c + 1 < nch) {
            int k0 = (c + 1) << 5;
            const float* pa = Ab + (long)(bm + ar0) * lda + k0 + acg * 4;
            #pragma unroll
            for (int l = 0; l < 4; l++) ra[l] = *(const float4*)(pa + (long)(32 * l) * lda);
            if (TRB) {
                const float* pb = Bb + (long)(bn + ar0) * ldb + k0 + acg * 4;
                #pragma unroll
                for (int l = 0; l < 4; l++) rb[l] = *(const float4*)(pb + (long)(32 * l) * ldb);
            } else {
                const float* pb = Bb + (long)(k0 + warp) * ldb + bn + lane * 4;
                #pragma unroll
                for (int l = 0; l < 4; l++) rb[l] = *(const float4*)(pb + (long)(8 * l) * ldb);
            }
        }

        #pragma unroll
        for (int ks = 0; ks < 4; ks++) {
            int kk = ks * 8 + tig;
            unsigned a[2][4];
            #pragma unroll
            for (int mt = 0; mt < 2; mt++) {
                const unsigned* ap = &As[(wm * 32 + mt * 16 + gid) * PA + kk];
                a[mt][0] = ap[0];
                a[mt][1] = ap[8 * PA];
                a[mt][2] = ap[4];
                a[mt][3] = ap[8 * PA + 4];
            }
            #pragma unroll
            for (int nt = 0; nt < 8; nt++) {
                int ncol = wn * 64 + nt * 8 + gid;
                unsigned b0, b1;
                if (TRB) {
                    const unsigned* bp = &Bs[ncol * PA + kk];
                    b0 = bp[0]; b1 = bp[4];
                } else {
                    const unsigned* bp = &Bs[kk * PB + ncol];
                    b0 = bp[0]; b1 = bp[4 * PB];
                }
                mma_tf32(acc[0][nt], a[0], b0, b1);
                mma_tf32(acc[1][nt], a[1], b0, b1);
            }
        }
        if (c + 1 < nch) __syncthreads();
    }

    #pragma unroll
    for (int mt = 0; mt < 2; mt++) {
        int r0 = bm + wm * 32 + mt * 16 + gid;
        #pragma unroll
        for (int nt = 0; nt < 8; nt++) {
            int c0 = bn + wn * 64 + nt * 8 + tig * 2;
            float v0 = acc[mt][nt][0] * alpha;
            float v1 = acc[mt][nt][1] * alpha;
            float v2 = acc[mt][nt][2] * alpha;
            float v3 = acc[mt][nt][3] * alpha;
            if (bias) {
                float b0v = bias[c0], b1v = bias[c0 + 1];
                v0 += b0v; v1 += b1v; v2 += b0v; v3 += b1v;
            }
            if (prelu) {
                float p0 = prelu[c0], p1 = prelu[c0 + 1];
                v0 = v0 > 0.f ? v0 : v0 * p0;
                v1 = v1 > 0.f ? v1 : v1 * p1;
                v2 = v2 > 0.f ? v2 : v2 * p0;
                v3 = v3 > 0.f ? v3 : v3 * p1;
            }
            if (Rb) {
                float2 q0 = *(const float2*)(Rb + (long)r0 * ldc + c0);
                float2 q1 = *(const float2*)(Rb + (long)(r0 + 8) * ldc + c0);
                v0 += q0.x; v1 += q0.y; v2 += q1.x; v3 += q1.y;
            }
            *(float2*)(Cb + (long)r0 * ldc + c0)       = make_float2(v0, v1);
            *(float2*)(Cb + (long)(r0 + 8) * ldc + c0) = make_float2(v2, v3);
        }
    }
}

// ---------------- layer norm over rows of 512 ----------------
__global__ void __launch_bounds__(128) layernorm_kernel(
    const float* __restrict__ in, float* __restrict__ out,
    const float* __restrict__ gamma, const float* __restrict__ beta)
{
    long row = blockIdx.x;
    int tid = threadIdx.x, lane = tid & 31, wid = tid >> 5;
    float4 v = ((const float4*)(in + row * HSZ))[tid];

    __shared__ float red[8];
    float s = v.x + v.y + v.z + v.w;
    #pragma unroll
    for (int o = 16; o > 0; o >>= 1) s += __shfl_xor_sync(0xffffffffu, s, o);
    if (lane == 0) red[wid] = s;
    __syncthreads();
    float mu = (red[0] + red[1] + red[2] + red[3]) * (1.f / HSZ);

    float dx = v.x - mu, dy = v.y - mu, dz = v.z - mu, dw = v.w - mu;
    float q = dx*dx + dy*dy + dz*dz + dw*dw;
    #pragma unroll
    for (int o = 16; o > 0; o >>= 1) q += __shfl_xor_sync(0xffffffffu, q, o);
    if (lane == 0) red[4 + wid] = q;
    __syncthreads();
    float var = (red[4] + red[5] + red[6] + red[7]) * (1.f / HSZ);
    float rstd = rsqrtf(var + 1e-5f);

    float4 g = ((const float4*)gamma)[tid];
    float4 bb = ((const float4*)beta)[tid];
    float4 o4;
    o4.x = dx * rstd * g.x + bb.x;
    o4.y = dy * rstd * g.y + bb.y;
    o4.z = dz * rstd * g.z + bb.z;
    o4.w = dw * rstd * g.w + bb.w;
    ((float4*)(out + row * HSZ))[tid] = o4;
}

// ---------------- output assembly: [glob | nodes | mask] ----------------
__global__ void __launch_bounds__(256) write_out_kernel(float* __restrict__ out, long out_size)
{
    long i = (long)blockIdx.x * 256 + threadIdx.x;
    if (i >= out_size) return;
    const long G  = (long)BB * HSZ;                 // 8192
    const long ND = (long)BB * NN * HSZ;            // 8388608
    if (i < G) {
        long b = i >> 9;
        long c = i & 511;
        out[i] = g_x[(b * NN + EE) * HSZ + c];
    } else if (i < G + ND) {
        out[i] = g_x[i - G];
    } else {
        out[i] = 1.0f;
    }
}

// ---------------- orchestration ----------------
extern "C" void kernel_launch(void* const* d_in, const int* in_sizes, int n_in,
                              void* d_out, int out_size)
{
    const float* ents = (const float*)d_in[0];
    const int*   rels = (const int*)  d_in[1];
    const int*   adj  = (const int*)  d_in[2];
    const float* renc = (const float*)d_in[3];
    const float* Wq   = (const float*)d_in[4];
    const float* Wk   = (const float*)d_in[5];
    const float* Wv   = (const float*)d_in[6];
    const float* l1w  = (const float*)d_in[7];
    const float* l1b  = (const float*)d_in[8];
    const float* l2w  = (const float*)d_in[9];
    const float* l2b  = (const float*)d_in[10];
    const float* ln1s = (const float*)d_in[11];
    const float* ln1b = (const float*)d_in[12];
    const float* ln2s = (const float*)d_in[13];
    const float* ln2b = (const float*)d_in[14];
    const float* pa   = (const float*)d_in[15];

    float *gx, *gq, *gk, *gv, *go, *gt, *gh;
    cudaGetSymbolAddress((void**)&gx, g_x);
    cudaGetSymbolAddress((void**)&gq, g_q);
    cudaGetSymbolAddress((void**)&gk, g_k);
    cudaGetSymbolAddress((void**)&gv, g_v);
    cudaGetSymbolAddress((void**)&go, g_o);
    cudaGetSymbolAddress((void**)&gt, g_t);
    cudaGetSymbolAddress((void**)&gh, g_h);

    cudaFuncSetAttribute(flash_kernel, cudaFuncAttributeMaxDynamicSharedMemorySize, FL_BYTES);

    const long M = (long)BB * NN;                   // 16384

    // gather x
    {
        long tot = M * (HSZ/4);
        gather_kernel<<<(unsigned)((tot + 255) / 256), 256>>>(ents, rels, renc);
    }
    // adj -> bitmask (once; constant across layers)
    {
        long tot = (long)BB * NN * (NN/32);
        mask_kernel<<<(unsigned)((tot + 255) / 256), 256>>>(adj);
    }

    for (int j = 0; j < PROP; j++) {
        const float* wq = Wq + (long)j * HSZ * HSZ;
        const float* wk = Wk + (long)j * HSZ * HSZ;
        const float* wv = Wv + (long)j * HSZ * HSZ;

        // Q,K,V = x @ W*
        gemm_mma<false><<<dim3(HSZ/128, (unsigned)(M/128), 1), 256>>>(
            gx, wq, gq, (int)M, HSZ, HSZ, HSZ, HSZ, HSZ,
            0,0,0,0,0,0, 1, 1.f, nullptr, nullptr, nullptr);
        gemm_mma<false><<<dim3(HSZ/128, (unsigned)(M/128), 1), 256>>>(
            gx, wk, gk, (int)M, HSZ, HSZ, HSZ, HSZ, HSZ,
            0,0,0,0,0,0, 1, 1.f, nullptr, nullptr, nullptr);
        gemm_mma<false><<<dim3(HSZ/128, (unsigned)(M/128), 1), 256>>>(
            gx, wv, gv, (int)M, HSZ, HSZ, HSZ, HSZ, HSZ,
            0,0,0,0,0,0, 1, 1.f, nullptr, nullptr, nullptr);

        // fused: S=QK^T/sqrt, mask, softmax, @V, +x  -> g_o
        flash_kernel<<<dim3(NN/128, HEADS, BB), 256, FL_BYTES>>>(gq, gk, gv, gx, go);

        // t = LN1(out)
        layernorm_kernel<<<(unsigned)M, 128>>>(go, gt, ln1s + j*HSZ, ln1b + j*HSZ);

        // h = prelu(t @ l1_w + l1_b)
        gemm_mma<false><<<dim3(DFF/128, (unsigned)(M/128), 1), 256>>>(
            gt, l1w + (long)j*HSZ*DFF, gh, (int)M, DFF, HSZ, HSZ, DFF, DFF,
            0,0,0,0,0,0, 1, 1.f, l1b + (long)j*DFF, pa + (long)j*DFF, nullptr);

        // o = h @ l2_w + l2_b + t
        gemm_mma<false><<<dim3(HSZ/128, (unsigned)(M/128), 1), 256>>>(
            gh, l2w + (long)j*DFF*HSZ, go, (int)M, HSZ, DFF, DFF, HSZ, HSZ,
            0,0,0,0,0,0, 1, 1.f, l2b + (long)j*HSZ, nullptr, gt);

        // x = LN2(o)
        layernorm_kernel<<<(unsigned)M, 128>>>(go, gx, ln2s + j*HSZ, ln2b + j*HSZ);
    }

    // assemble output
    {
        long os = (long)out_size;
        write_out_kernel<<<(unsigned)((os + 255) / 256), 256>>>((float*)d_out, os);
    }
}

// round 8
// speedup vs baseline: 1.1020x; 1.1020x over previous
#include <cuda_runtime.h>
#include <cuda_bf16.h>
#include <float.h>
#include <math.h>

// ---------------- problem constants ----------------
#define BB   16
#define EE   400
#define RR   624
#define NN   1024          // E + R
#define HSZ  512
#define HEADS 4
#define DK   128
#define DFF  2048
#define PROP 2
#define RTOKS 40

// ---------------- scratch (device globals; no allocs allowed) ----------------
__device__ float g_x[(long)BB*NN*HSZ];
__device__ float g_q[(long)BB*NN*HSZ];
__device__ float g_k[(long)BB*NN*HSZ];
__device__ float g_v[(long)BB*NN*HSZ];
__device__ float g_o[(long)BB*NN*HSZ];
__device__ float g_t[(long)BB*NN*HSZ];
__device__ float g_h[(long)BB*NN*DFF];
__device__ unsigned g_mask[(long)BB*NN*(NN/32)];   // adj bitmask, 2MB

// ---------------- helpers ----------------
__device__ __forceinline__ unsigned f2tf32(float x) {
    unsigned r;
    asm("cvt.rna.tf32.f32 %0, %1;" : "=r"(r) : "f"(x));
    return r;
}

__device__ __forceinline__ void mma_tf32(float* c, const unsigned* a, unsigned b0, unsigned b1) {
    asm volatile(
        "mma.sync.aligned.m16n8k8.row.col.f32.tf32.tf32.f32 "
        "{%0,%1,%2,%3}, {%4,%5,%6,%7}, {%8,%9}, {%0,%1,%2,%3};\n"
        : "+f"(c[0]), "+f"(c[1]), "+f"(c[2]), "+f"(c[3])
        : "r"(a[0]), "r"(a[1]), "r"(a[2]), "r"(a[3]), "r"(b0), "r"(b1));
}

__device__ __forceinline__ void cp16(unsigned dst, const void* src) {
    asm volatile("cp.async.cg.shared.global [%0], [%1], 16;" :: "r"(dst), "l"(src) : "memory");
}
__device__ __forceinline__ void cp_commit() {
    asm volatile("cp.async.commit_group;" ::: "memory");
}

// ---------------- gather: x = concat(ents, renc[rels]) ----------------
__global__ void __launch_bounds__(256) gather_kernel(
    const float* __restrict__ ents, const int* __restrict__ rels,
    const float* __restrict__ renc)
{
    long i = (long)blockIdx.x * 256 + threadIdx.x;          // float4 index
    const long TOT = (long)BB * NN * (HSZ / 4);
    if (i >= TOT) return;
    int c  = (int)(i & (HSZ/4 - 1));                        // 0..127
    long bn = i >> 7;
    int n  = (int)(bn & (NN - 1));
    int b  = (int)(bn >> 10);
    float4 v;
    if (n < EE) {
        v = ((const float4*)ents)[((long)b*EE + n)*(HSZ/4) + c];
    } else {
        int r = rels[b*RR + (n - EE)];
        v = ((const float4*)renc)[(long)r*(HSZ/4) + c];
    }
    ((float4*)g_x)[i] = v;
}

// ---------------- adj -> bitmask (32 cols per word) ----------------
__global__ void __launch_bounds__(256) mask_kernel(const int* __restrict__ adj)
{
    long i = (long)blockIdx.x * 256 + threadIdx.x;          // word index
    const long TOT = (long)BB * NN * (NN / 32);
    if (i >= TOT) return;
    const int* p = adj + i * 32;
    unsigned m = 0;
    #pragma unroll
    for (int t = 0; t < 8; t++) {
        int4 a = ((const int4*)p)[t];
        m |= (a.x ? 1u : 0u) << (t*4 + 0);
        m |= (a.y ? 1u : 0u) << (t*4 + 1);
        m |= (a.z ? 1u : 0u) << (t*4 + 2);
        m |= (a.w ? 1u : 0u) << (t*4 + 3);
    }
    g_mask[i] = m;
}

// ---------------- fused flash attention (masked) + residual ----------------
// Per block: 128 Q rows for one (b,h). 8 warps, warp w owns rows [w*16, w*16+16).
// smem: sQ[128][136] (tf32), bufK[128][136] (raw fp32 via cp.async),
//       bufV[128][136] (raw fp32 via cp.async). P stays in registers (shfl->frag).
#define FL_STRIDE 136
#define FL_WORDS  (128 * FL_STRIDE)
#define FL_BYTES  (3 * FL_WORDS * 4)
#define FL_NT     (NN / 128)

__global__ void __launch_bounds__(256) flash_kernel(
    const float* __restrict__ Q, const float* __restrict__ K,
    const float* __restrict__ V, const float* __restrict__ X,
    float* __restrict__ O)
{
    extern __shared__ unsigned sm[];
    unsigned* sQ   = sm;
    unsigned* bufK = sm + FL_WORDS;
    unsigned* bufV = sm + 2 * FL_WORDS;
    unsigned sbase = (unsigned)__cvta_generic_to_shared(sm);

    int qt = blockIdx.x, h = blockIdx.y, b = blockIdx.z;
    int tid = threadIdx.x, warp = tid >> 5, lane = tid & 31;
    int gid = lane >> 2, tig = lane & 3;

    const float scale = 0.04419417382415922f;  // 1/sqrt(512)
    const long baserow = (long)b * NN;
    const int  hc = h * DK;

    const float* Kbase = K + baserow * HSZ + hc;
    const float* Vbase = V + baserow * HSZ + hc;

    // cp.async a 128x128 fp32 tile into smem words [dstW, dstW + FL_WORDS)
    auto cp_tile = [&](unsigned dstW, const float* src) {
        #pragma unroll
        for (int t = 0; t < 16; t++) {
            int i = tid + t * 256;
            int r = i >> 5, c4 = (i & 31) << 2;
            cp16(sbase + (dstW + r * FL_STRIDE + c4) * 4, src + (long)r * HSZ + c4);
        }
    };

    // ---- issue K0 and V0 prefetch first, then load Q (LDG overlaps cp.async) ----
    cp_tile(FL_WORDS, Kbase);                cp_commit();     // G0 = K0
    cp_tile(2 * FL_WORDS, Vbase);            cp_commit();     // G1 = V0

    {
        const float* src = Q + (baserow + qt*128) * HSZ + hc;
        for (int i = tid; i < 128*32; i += 256) {
            int r = i >> 5, c4 = (i & 31) * 4;
            float4 v = *(const float4*)(src + (long)r * HSZ + c4);
            unsigned* d = &sQ[r * FL_STRIDE + c4];
            d[0] = f2tf32(v.x * scale); d[1] = f2tf32(v.y * scale);
            d[2] = f2tf32(v.z * scale); d[3] = f2tf32(v.w * scale);
        }
    }

    float acc_o[16][4];
    #pragma unroll
    for (int nt = 0; nt < 16; nt++)
        #pragma unroll
        for (int i = 0; i < 4; i++) acc_o[nt][i] = 0.f;

    float m0 = -INFINITY, m1 = -INFINITY, l0 = 0.f, l1 = 0.f;

    const unsigned* mrow0 = g_mask + ((long)b*NN + qt*128 + warp*16 + gid) * (NN/32);
    const unsigned* mrow1 = mrow0 + 8 * (NN/32);

    float acc_s[16][4];

    for (int j = 0; j < FL_NT; j++) {
        // ---- wait K_j (newest group may still be in flight) ----
        asm volatile("cp.async.wait_group 1;" ::: "memory");
        __syncthreads();

        // ---- S = Qs @ K^T  (warp: 16 rows x 128 cols) ----
        #pragma unroll
        for (int nt = 0; nt < 16; nt++)
            #pragma unroll
            for (int i = 0; i < 4; i++) acc_s[nt][i] = 0.f;

        #pragma unroll
        for (int ks = 0; ks < 16; ks++) {
            int k0 = ks * 8;
            unsigned a[4];
            const unsigned* ap = &sQ[(warp*16 + gid) * FL_STRIDE + k0 + tig];
            a[0] = ap[0]; a[1] = ap[8*FL_STRIDE]; a[2] = ap[4]; a[3] = ap[8*FL_STRIDE + 4];
            #pragma unroll
            for (int nt = 0; nt < 16; nt++) {
                const unsigned* bp = &bufK[(nt*8 + gid) * FL_STRIDE + k0 + tig];
                mma_tf32(acc_s[nt], a, bp[0], bp[4]);
            }
        }

        __syncthreads();                      // all warps done reading bufK
        if (j + 1 < FL_NT) {                  // prefetch K_{j+1} over softmax + O-gemm
            cp_tile(FL_WORDS, Kbase + (long)(j+1)*128 * HSZ);
            cp_commit();
        }

        // ---- mask + online softmax (registers only) ----
        unsigned mw0[4], mw1[4];
        #pragma unroll
        for (int w = 0; w < 4; w++) { mw0[w] = mrow0[j*4 + w]; mw1[w] = mrow1[j*4 + w]; }

        float tm0 = -INFINITY, tm1 = -INFINITY;
        #pragma unroll
        for (int nt = 0; nt < 16; nt++) {
            int c0 = nt*8 + tig*2;
            unsigned w = nt >> 2;
            int bi = c0 & 31;
            acc_s[nt][0] = ((mw0[w] >> bi)     & 1) ? acc_s[nt][0] : -1e30f;
            acc_s[nt][1] = ((mw0[w] >> (bi+1)) & 1) ? acc_s[nt][1] : -1e30f;
            acc_s[nt][2] = ((mw1[w] >> bi)     & 1) ? acc_s[nt][2] : -1e30f;
            acc_s[nt][3] = ((mw1[w] >> (bi+1)) & 1) ? acc_s[nt][3] : -1e30f;
            tm0 = fmaxf(tm0, fmaxf(acc_s[nt][0], acc_s[nt][1]));
            tm1 = fmaxf(tm1, fmaxf(acc_s[nt][2], acc_s[nt][3]));
        }
        tm0 = fmaxf(tm0, __shfl_xor_sync(0xffffffffu, tm0, 1));
        tm0 = fmaxf(tm0, __shfl_xor_sync(0xffffffffu, tm0, 2));
        tm1 = fmaxf(tm1, __shfl_xor_sync(0xffffffffu, tm1, 1));
        tm1 = fmaxf(tm1, __shfl_xor_sync(0xffffffffu, tm1, 2));

        float nm0 = fmaxf(m0, tm0), nm1 = fmaxf(m1, tm1);
        float f0 = __expf(m0 - nm0), f1 = __expf(m1 - nm1);

        float sum0 = 0.f, sum1 = 0.f;
        #pragma unroll
        for (int nt = 0; nt < 16; nt++) {
            float p0 = __expf(acc_s[nt][0] - nm0);
            float p1 = __expf(acc_s[nt][1] - nm0);
            float p2 = __expf(acc_s[nt][2] - nm1);
            float p3 = __expf(acc_s[nt][3] - nm1);
            sum0 += p0 + p1; sum1 += p2 + p3;
            acc_s[nt][0] = p0; acc_s[nt][1] = p1;
            acc_s[nt][2] = p2; acc_s[nt][3] = p3;
        }
        sum0 += __shfl_xor_sync(0xffffffffu, sum0, 1);
        sum0 += __shfl_xor_sync(0xffffffffu, sum0, 2);
        sum1 += __shfl_xor_sync(0xffffffffu, sum1, 1);
        sum1 += __shfl_xor_sync(0xffffffffu, sum1, 2);

        l0 = l0 * f0 + sum0;  l1 = l1 * f1 + sum1;
        m0 = nm0;  m1 = nm1;
        #pragma unroll
        for (int nt = 0; nt < 16; nt++) {
            acc_o[nt][0] *= f0; acc_o[nt][1] *= f0;
            acc_o[nt][2] *= f1; acc_o[nt][3] *= f1;
        }

        // ---- wait V_j ----
        if (j + 1 < FL_NT) asm volatile("cp.async.wait_group 1;" ::: "memory");
        else               asm volatile("cp.async.wait_group 0;" ::: "memory");
        __syncthreads();

        // ---- O += P @ V  (P acc-layout -> A-frag via quad shuffles) ----
        const int s0 = tig >> 1;
        const bool odd = (tig & 1);
        #pragma unroll
        for (int ks = 0; ks < 16; ks++) {
            float p0 = acc_s[ks][0], p1 = acc_s[ks][1];
            float p2 = acc_s[ks][2], p3 = acc_s[ks][3];
            float q0a = __shfl_sync(0xffffffffu, p0, s0, 4);
            float q0b = __shfl_sync(0xffffffffu, p1, s0, 4);
            float q1a = __shfl_sync(0xffffffffu, p2, s0, 4);
            float q1b = __shfl_sync(0xffffffffu, p3, s0, 4);
            float q2a = __shfl_sync(0xffffffffu, p0, s0 + 2, 4);
            float q2b = __shfl_sync(0xffffffffu, p1, s0 + 2, 4);
            float q3a = __shfl_sync(0xffffffffu, p2, s0 + 2, 4);
            float q3b = __shfl_sync(0xffffffffu, p3, s0 + 2, 4);
            unsigned a[4];
            a[0] = f2tf32(odd ? q0b : q0a);
            a[1] = f2tf32(odd ? q1b : q1a);
            a[2] = f2tf32(odd ? q2b : q2a);
            a[3] = f2tf32(odd ? q3b : q3a);

            int k0 = ks * 8;
            #pragma unroll
            for (int nt = 0; nt < 16; nt++) {
                const unsigned* bp = &bufV[(k0 + tig) * FL_STRIDE + nt*8 + gid];
                mma_tf32(acc_o[nt], a, bp[0], bp[4*FL_STRIDE]);
            }
        }

        if (j + 1 < FL_NT) {
            __syncthreads();                  // all warps done reading bufV
            cp_tile(2 * FL_WORDS, Vbase + (long)(j+1)*128 * HSZ);
            cp_commit();
        }
    }

    // ---- epilogue: O/l + residual X ----
    float inv0 = 1.f / l0, inv1 = 1.f / l1;
    long rbase = (baserow + qt*128 + warp*16 + gid) * HSZ + hc;
    #pragma unroll
    for (int nt = 0; nt < 16; nt++) {
        int c0 = nt*8 + tig*2;
        float2 x0 = *(const float2*)(X + rbase + c0);
        float2 x1 = *(const float2*)(X + rbase + 8*HSZ + c0);
        float2 o0 = make_float2(acc_o[nt][0]*inv0 + x0.x, acc_o[nt][1]*inv0 + x0.y);
        float2 o1 = make_float2(acc_o[nt][2]*inv1 + x1.x, acc_o[nt][3]*inv1 + x1.y);
        *(float2*)(O + rbase + c0)           = o0;
        *(float2*)(O + rbase + 8*HSZ + c0)   = o1;
    }
}

// ---------------- tensor-core tf32 GEMM: 128x128 block tile, K-chunk 32 ----------------
template<bool TRB>
__global__ void __launch_bounds__(256, 2) gemm_mma(
    const float* __restrict__ A, const float* __restrict__ B, float* __restrict__ C,
    int M, int N, int K, int lda, int ldb, int ldc,
    long sAb, long sAh, long sBb, long sBh, long sCb, long sCh,
    int H, float alpha,
    const float* __restrict__ bias,
    const float* __restrict__ prelu,
    const float* __restrict__ res)
{
    constexpr int PA = 40;
    constexpr int PB = 136;

    __shared__ unsigned As[128 * PA];
    __shared__ unsigned Bs[TRB ? 128 * PA : 32 * PB];

    int zb = blockIdx.z / H;
    int zh = blockIdx.z - zb * H;
    const float* Ab = A + zb * sAb + zh * sAh;
    const float* Bb = B + zb * sBb + zh * sBh;
    float*       Cb = C + zb * sCb + zh * sCh;
    const float* Rb = res ? (res + zb * sCb + zh * sCh) : nullptr;

    int bm = blockIdx.y << 7;
    int bn = blockIdx.x << 7;

    int tid  = threadIdx.x;
    int warp = tid >> 5, lane = tid & 31;
    int wm = warp >> 1, wn = warp & 1;
    int gid = lane >> 2, tig = lane & 3;

    float acc[2][8][4];
    #pragma unroll
    for (int mt = 0; mt < 2; mt++)
        #pragma unroll
        for (int nt = 0; nt < 8; nt++)
            #pragma unroll
            for (int i = 0; i < 4; i++) acc[mt][nt][i] = 0.f;

    const int ar0 = tid >> 3;
    const int acg = tid & 7;

    float4 ra[4], rb[4];
    const int nch = K >> 5;

    {
        const float* pa = Ab + (long)(bm + ar0) * lda + acg * 4;
        #pragma unroll
        for (int l = 0; l < 4; l++) ra[l] = *(const float4*)(pa + (long)(32 * l) * lda);
        if (TRB) {
            const float* pb = Bb + (long)(bn + ar0) * ldb + acg * 4;
            #pragma unroll
            for (int l = 0; l < 4; l++) rb[l] = *(const float4*)(pb + (long)(32 * l) * ldb);
        } else {
            const float* pb = Bb + (long)warp * ldb + bn + lane * 4;
            #pragma unroll
            for (int l = 0; l < 4; l++) rb[l] = *(const float4*)(pb + (long)(8 * l) * ldb);
        }
    }

    for (int c = 0; c < nch; c++) {
        #pragma unroll
        for (int l = 0; l < 4; l++) {
            uint4 u;
            u.x = f2tf32(ra[l].x); u.y = f2tf32(ra[l].y);
            u.z = f2tf32(ra[l].z); u.w = f2tf32(ra[l].w);
            *(uint4*)&As[(ar0 + 32 * l) * PA + acg * 4] = u;
        }
        #pragma unroll
        for (int l = 0; l < 4; l++) {
            uint4 u;
            u.x = f2tf32(rb[l].x); u.y = f2tf32(rb[l].y);
            u.z = f2tf32(rb[l].z); u.w = f2tf32(rb[l].w);
            if (TRB) *(uint4*)&Bs[(ar0 + 32 * l) * PA + acg * 4] = u;
            else     *(uint4*)&Bs[(warp + 8 * l) * PB + lane * 4] = u;
        }
        __syncthreads();

        if (c + 1 < nch) {
            int k0 = (c + 1) << 5;
            const float* pa = Ab + (long)(bm + ar0) * lda + k0 + acg * 4;
            #pragma unroll
            for (int l = 0; l < 4; l++) ra[l] = *(const float4*)(pa + (long)(32 * l) * lda);
            if (TRB) {
                const float* pb = Bb + (long)(bn + ar0) * ldb + k0 + acg * 4;
                #pragma unroll
                for (int l = 0; l < 4; l++) rb[l] = *(const float4*)(pb + (long)(32 * l) * ldb);
            } else {
                const float* pb = Bb + (long)(k0 + warp) * ldb + bn + lane * 4;
                #pragma unroll
                for (int l = 0; l < 4; l++) rb[l] = *(const float4*)(pb + (long)(8 * l) * ldb);
            }
        }

        #pragma unroll
        for (int ks = 0; ks < 4; ks++) {
            int kk = ks * 8 + tig;
            unsigned a[2][4];
            #pragma unroll
            for (int mt = 0; mt < 2; mt++) {
                const unsigned* ap = &As[(wm * 32 + mt * 16 + gid) * PA + kk];
                a[mt][0] = ap[0];
                a[mt][1] = ap[8 * PA];
                a[mt][2] = ap[4];
                a[mt][3] = ap[8 * PA + 4];
            }
            #pragma unroll
            for (int nt = 0; nt < 8; nt++) {
                int ncol = wn * 64 + nt * 8 + gid;
                unsigned b0, b1;
                if (TRB) {
                    const unsigned* bp = &Bs[ncol * PA + kk];
                    b0 = bp[0]; b1 = bp[4];
                } else {
                    const unsigned* bp = &Bs[kk * PB + ncol];
                    b0 = bp[0]; b1 = bp[4 * PB];
                }
                mma_tf32(acc[0][nt], a[0], b0, b1);
                mma_tf32(acc[1][nt], a[1], b0, b1);
            }
        }
        if (c + 1 < nch) __syncthreads();
    }

    #pragma unroll
    for (int mt = 0; mt < 2; mt++) {
        int r0 = bm + wm * 32 + mt * 16 + gid;
        #pragma unroll
        for (int nt = 0; nt < 8; nt++) {
            int c0 = bn + wn * 64 + nt * 8 + tig * 2;
            float v0 = acc[mt][nt][0] * alpha;
            float v1 = acc[mt][nt][1] * alpha;
            float v2 = acc[mt][nt][2] * alpha;
            float v3 = acc[mt][nt][3] * alpha;
            if (bias) {
                float b0v = bias[c0], b1v = bias[c0 + 1];
                v0 += b0v; v1 += b1v; v2 += b0v; v3 += b1v;
            }
            if (prelu) {
                float p0 = prelu[c0], p1 = prelu[c0 + 1];
                v0 = v0 > 0.f ? v0 : v0 * p0;
                v1 = v1 > 0.f ? v1 : v1 * p1;
                v2 = v2 > 0.f ? v2 : v2 * p0;
                v3 = v3 > 0.f ? v3 : v3 * p1;
            }
            if (Rb) {
                float2 q0 = *(const float2*)(Rb + (long)r0 * ldc + c0);
                float2 q1 = *(const float2*)(Rb + (long)(r0 + 8) * ldc + c0);
                v0 += q0.x; v1 += q0.y; v2 += q1.x; v3 += q1.y;
            }
            *(float2*)(Cb + (long)r0 * ldc + c0)       = make_float2(v0, v1);
            *(float2*)(Cb + (long)(r0 + 8) * ldc + c0) = make_float2(v2, v3);
        }
    }
}

// ---------------- layer norm over rows of 512 ----------------
__global__ void __launch_bounds__(128) layernorm_kernel(
    const float* __restrict__ in, float* __restrict__ out,
    const float* __restrict__ gamma, const float* __restrict__ beta)
{
    long row = blockIdx.x;
    int tid = threadIdx.x, lane = tid & 31, wid = tid >> 5;
    float4 v = ((const float4*)(in + row * HSZ))[tid];

    __shared__ float red[8];
    float s = v.x + v.y + v.z + v.w;
    #pragma unroll
    for (int o = 16; o > 0; o >>= 1) s += __shfl_xor_sync(0xffffffffu, s, o);
    if (lane == 0) red[wid] = s;
    __syncthreads();
    float mu = (red[0] + red[1] + red[2] + red[3]) * (1.f / HSZ);

    float dx = v.x - mu, dy = v.y - mu, dz = v.z - mu, dw = v.w - mu;
    float q = dx*dx + dy*dy + dz*dz + dw*dw;
    #pragma unroll
    for (int o = 16; o > 0; o >>= 1) q += __shfl_xor_sync(0xffffffffu, q, o);
    if (lane == 0) red[4 + wid] = q;
    __syncthreads();
    float var = (red[4] + red[5] + red[6] + red[7]) * (1.f / HSZ);
    float rstd = rsqrtf(var + 1e-5f);

    float4 g = ((const float4*)gamma)[tid];
    float4 bb = ((const float4*)beta)[tid];
    float4 o4;
    o4.x = dx * rstd * g.x + bb.x;
    o4.y = dy * rstd * g.y + bb.y;
    o4.z = dz * rstd * g.z + bb.z;
    o4.w = dw * rstd * g.w + bb.w;
    ((float4*)(out + row * HSZ))[tid] = o4;
}

// ---------------- output assembly: [glob | nodes | mask] ----------------
__global__ void __launch_bounds__(256) write_out_kernel(float* __restrict__ out, long out_size)
{
    long i = (long)blockIdx.x * 256 + threadIdx.x;
    if (i >= out_size) return;
    const long G  = (long)BB * HSZ;                 // 8192
    const long ND = (long)BB * NN * HSZ;            // 8388608
    if (i < G) {
        long b = i >> 9;
        long c = i & 511;
        out[i] = g_x[(b * NN + EE) * HSZ + c];
    } else if (i < G + ND) {
        out[i] = g_x[i - G];
    } else {
        out[i] = 1.0f;
    }
}

// ---------------- orchestration ----------------
extern "C" void kernel_launch(void* const* d_in, const int* in_sizes, int n_in,
                              void* d_out, int out_size)
{
    const float* ents = (const float*)d_in[0];
    const int*   rels = (const int*)  d_in[1];
    const int*   adj  = (const int*)  d_in[2];
    const float* renc = (const float*)d_in[3];
    const float* Wq   = (const float*)d_in[4];
    const float* Wk   = (const float*)d_in[5];
    const float* Wv   = (const float*)d_in[6];
    const float* l1w  = (const float*)d_in[7];
    const float* l1b  = (const float*)d_in[8];
    const float* l2w  = (const float*)d_in[9];
    const float* l2b  = (const float*)d_in[10];
    const float* ln1s = (const float*)d_in[11];
    const float* ln1b = (const float*)d_in[12];
    const float* ln2s = (const float*)d_in[13];
    const float* ln2b = (const float*)d_in[14];
    const float* pa   = (const float*)d_in[15];

    float *gx, *gq, *gk, *gv, *go, *gt, *gh;
    cudaGetSymbolAddress((void**)&gx, g_x);
    cudaGetSymbolAddress((void**)&gq, g_q);
    cudaGetSymbolAddress((void**)&gk, g_k);
    cudaGetSymbolAddress((void**)&gv, g_v);
    cudaGetSymbolAddress((void**)&go, g_o);
    cudaGetSymbolAddress((void**)&gt, g_t);
    cudaGetSymbolAddress((void**)&gh, g_h);

    cudaFuncSetAttribute(flash_kernel, cudaFuncAttributeMaxDynamicSharedMemorySize, FL_BYTES);

    const long M = (long)BB * NN;                   // 16384

    // gather x
    {
        long tot = M * (HSZ/4);
        gather_kernel<<<(unsigned)((tot + 255) / 256), 256>>>(ents, rels, renc);
    }
    // adj -> bitmask (once; constant across layers)
    {
        long tot = (long)BB * NN * (NN/32);
        mask_kernel<<<(unsigned)((tot + 255) / 256), 256>>>(adj);
    }

    for (int j = 0; j < PROP; j++) {
        const float* wq = Wq + (long)j * HSZ * HSZ;
        const float* wk = Wk + (long)j * HSZ * HSZ;
        const float* wv = Wv + (long)j * HSZ * HSZ;

        // Q,K,V = x @ W*
        gemm_mma<false><<<dim3(HSZ/128, (unsigned)(M/128), 1), 256>>>(
            gx, wq, gq, (int)M, HSZ, HSZ, HSZ, HSZ, HSZ,
            0,0,0,0,0,0, 1, 1.f, nullptr, nullptr, nullptr);
        gemm_mma<false><<<dim3(HSZ/128, (unsigned)(M/128), 1), 256>>>(
            gx, wk, gk, (int)M, HSZ, HSZ, HSZ, HSZ, HSZ,
            0,0,0,0,0,0, 1, 1.f, nullptr, nullptr, nullptr);
        gemm_mma<false><<<dim3(HSZ/128, (unsigned)(M/128), 1), 256>>>(
            gx, wv, gv, (int)M, HSZ, HSZ, HSZ, HSZ, HSZ,
            0,0,0,0,0,0, 1, 1.f, nullptr, nullptr, nullptr);

        // fused: S=QK^T/sqrt, mask, softmax, @V, +x  -> g_o
        flash_kernel<<<dim3(NN/128, HEADS, BB), 256, FL_BYTES>>>(gq, gk, gv, gx, go);

        // t = LN1(out)
        layernorm_kernel<<<(unsigned)M, 128>>>(go, gt, ln1s + j*HSZ, ln1b + j*HSZ);

        // h = prelu(t @ l1_w + l1_b)
        gemm_mma<false><<<dim3(DFF/128, (unsigned)(M/128), 1), 256>>>(
            gt, l1w + (long)j*HSZ*DFF, gh, (int)M, DFF, HSZ, HSZ, DFF, DFF,
            0,0,0,0,0,0, 1, 1.f, l1b + (long)j*DFF, pa + (long)j*DFF, nullptr);

        // o = h @ l2_w + l2_b + t
        gemm_mma<false><<<dim3(HSZ/128, (unsigned)(M/128), 1), 256>>>(
            gh, l2w + (long)j*DFF*HSZ, go, (int)M, HSZ, DFF, DFF, HSZ, HSZ,
            0,0,0,0,0,0, 1, 1.f, l2b + (long)j*HSZ, nullptr, gt);

        // x = LN2(o)
        layernorm_kernel<<<(unsigned)M, 128>>>(go, gx, ln2s + j*HSZ, ln2b + j*HSZ);
    }

    // assemble output
    {
        long os = (long)out_size;
        write_out_kernel<<<(unsigned)((os + 255) / 256), 256>>>((float*)d_out, os);
    }
}